// round 5
// baseline (speedup 1.0000x reference)
#include <cuda_runtime.h>

#define HIDF 128
#define INF 16
#define OUTF 12
#define EPSF 1e-5f
#define NMAX 100000
#define EMAX 1600000
#define NSB  512

// ---------------- device scratch (static, no allocation) ----------------
__device__ int   g_bad;
__device__ int   g_esrc[EMAX];
__device__ int   g_edst[EMAX];
__device__ int   g_cnt[NMAX];
__device__ int   g_fill[NMAX];
__device__ int   g_rowptr[NMAX + 1];
__device__ int   g_bsumx[128];
__device__ int   g_src[EMAX];
__device__ float g_nrm[EMAX];
__device__ float g_dinv[NMAX];
__device__ __align__(16) float g_aggX[NMAX * INF];
__device__ __align__(16) float g_bufA[NMAX * HIDF];
__device__ __align__(16) float g_bufB[NMAX * HIDF];
__device__ __align__(16) float g_psum[NSB * HIDF];
__device__ __align__(16) float g_psq [NSB * HIDF];
__device__ __align__(16) float g_bn[2 * HIDF];   // [scale, shift]

static inline int cdiv(int a, int b) { return (a + b - 1) / b; }

// ---------------- edge_index dtype detect + repack ----------------
__global__ void k_det_init() { g_bad = 0; }

// If the buffer really is int64, every value (viewed as int64) lies in [0, n).
// If it's int32, the int64 view gives lo + hi*2^32 composites -> out of range.
__global__ void k_detect(const void* ei, int E, int n) {
    int e = blockIdx.x * blockDim.x + threadIdx.x;
    if (e < E) {
        long long v = ((const long long*)ei)[e];   // within first E*8 bytes = 2E int32, in bounds either way
        if (v < 0 || v >= (long long)n) g_bad = 1; // benign race
    }
}

__global__ void k_repack(const void* ei, int E) {
    int e = blockIdx.x * blockDim.x + threadIdx.x;
    if (e < E) {
        if (g_bad) {   // int32 layout
            const int* p = (const int*)ei;
            g_esrc[e] = p[e];
            g_edst[e] = p[E + e];
        } else {       // genuine int64 layout
            const long long* p = (const long long*)ei;
            g_esrc[e] = (int)p[e];
            g_edst[e] = (int)p[E + e];
        }
    }
}

// ---------------- CSR build (int atomics only) ----------------
__global__ void k_zero(int n) {
    int i = blockIdx.x * blockDim.x + threadIdx.x;
    if (i < n) { g_cnt[i] = 0; g_fill[i] = 0; }
}

__global__ void k_count(int E) {
    int e = blockIdx.x * blockDim.x + threadIdx.x;
    if (e < E) atomicAdd(&g_cnt[g_edst[e]], 1);
}

// 256 threads scan 1024 elements (4 per thread)
__global__ void k_scan_block(int n) {
    __shared__ int sh[256];
    int tid = threadIdx.x;
    int i0 = blockIdx.x * 1024 + tid * 4;
    int v0 = (i0 + 0 < n) ? g_cnt[i0 + 0] : 0;
    int v1 = (i0 + 1 < n) ? g_cnt[i0 + 1] : 0;
    int v2 = (i0 + 2 < n) ? g_cnt[i0 + 2] : 0;
    int v3 = (i0 + 3 < n) ? g_cnt[i0 + 3] : 0;
    int tot = v0 + v1 + v2 + v3;
    sh[tid] = tot;
    __syncthreads();
    for (int d = 1; d < 256; d <<= 1) {
        int t = (tid >= d) ? sh[tid - d] : 0;
        __syncthreads();
        sh[tid] += t;
        __syncthreads();
    }
    int run = sh[tid] - tot;
    run += v0; if (i0 + 0 < n) g_rowptr[i0 + 1] = run;
    run += v1; if (i0 + 1 < n) g_rowptr[i0 + 2] = run;
    run += v2; if (i0 + 2 < n) g_rowptr[i0 + 3] = run;
    run += v3; if (i0 + 3 < n) g_rowptr[i0 + 4] = run;
    if (tid == 255) g_bsumx[blockIdx.x] = sh[255];
}

__global__ void k_scan_bsum(int nb) {   // 1 block, 128 threads
    __shared__ int sh[128];
    int tid = threadIdx.x;
    int v = (tid < nb) ? g_bsumx[tid] : 0;
    sh[tid] = v;
    __syncthreads();
    for (int d = 1; d < 128; d <<= 1) {
        int t = (tid >= d) ? sh[tid - d] : 0;
        __syncthreads();
        sh[tid] += t;
        __syncthreads();
    }
    g_bsumx[tid] = sh[tid] - v;
}

__global__ void k_addoff(int n) {
    int i = blockIdx.x * blockDim.x + threadIdx.x;
    if (i < n) g_rowptr[i + 1] += g_bsumx[i >> 10];
    if (i == 0) g_rowptr[0] = 0;
}

__global__ void k_fillcsr(const float* w, int E) {
    int e = blockIdx.x * blockDim.x + threadIdx.x;
    if (e < E) {
        int dst = g_edst[e];
        int pos = atomicAdd(&g_fill[dst], 1);
        int idx = g_rowptr[dst] + pos;
        g_src[idx] = g_esrc[e];
        g_nrm[idx] = w[e];
    }
}

// ---------------- normalization (pure gather) ----------------
__global__ void k_deg(int n) {
    int i = blockIdx.x * blockDim.x + threadIdx.x;
    if (i < n) {
        int s0 = g_rowptr[i], s1 = g_rowptr[i + 1];
        float sum = 1.0f;
        for (int s = s0; s < s1; s++) sum += g_nrm[s];
        g_dinv[i] = rsqrtf(sum);
    }
}

__global__ void k_normfix(int n) {
    int i = blockIdx.x * blockDim.x + threadIdx.x;
    if (i < n) {
        float di = g_dinv[i];
        int s0 = g_rowptr[i], s1 = g_rowptr[i + 1];
        for (int s = s0; s < s1; s++)
            g_nrm[s] = g_dinv[g_src[s]] * g_nrm[s] * di;
    }
}

// ---------------- layer0 aggregation: x (16 feats) -> aggX ----------------
__global__ void k_agg16(const float* x, int n) {
    int t = blockIdx.x * blockDim.x + threadIdx.x;
    int node = t >> 4, f = t & 15;
    if (node < n) {
        float di = g_dinv[node];
        float a = x[node * INF + f] * di * di;
        int s0 = g_rowptr[node], s1 = g_rowptr[node + 1];
        for (int s = s0; s < s1; s++)
            a += x[g_src[s] * INF + f] * g_nrm[s];
        g_aggX[node * INF + f] = a;
    }
}

// ---------------- GEMM0: (N x 16) @ (16 x 128) + b -> bufA ----------------
__global__ void k_gemm0(const float* W, const float* bias, int n) {
    __shared__ float sW[INF * HIDF];
    __shared__ float sx[32 * INF];
    int tid = threadIdx.x;              // 128
    for (int idx = tid; idx < INF * HIDF; idx += 128) sW[idx] = W[idx];
    int base = blockIdx.x * 32;
    for (int idx = tid; idx < 32 * INF; idx += 128) {
        int r = idx >> 4, k = idx & 15;
        sx[idx] = (base + r < n) ? g_aggX[(base + r) * INF + k] : 0.0f;
    }
    __syncthreads();
    int col = tid;
    float wreg[INF];
#pragma unroll
    for (int k = 0; k < INF; k++) wreg[k] = sW[k * HIDF + col];
    float bb = bias[col];
    for (int r = 0; r < 32; r++) {
        if (base + r < n) {
            float acc = bb;
#pragma unroll
            for (int k = 0; k < INF; k++) acc += sx[r * INF + k] * wreg[k];
            g_bufA[(base + r) * HIDF + col] = acc;
        }
    }
}

// ---------------- BN: partial stats / finalize / apply ----------------
__global__ void k_stats(int n) {
    int col = threadIdx.x;              // 128
    int base = blockIdx.x * 256;
    float s = 0.0f, s2 = 0.0f;
    for (int r = 0; r < 256; r++) {
        int row = base + r;
        if (row < n) {
            float v = g_bufA[row * HIDF + col];
            s += v; s2 += v * v;
        }
    }
    g_psum[blockIdx.x * HIDF + col] = s;
    g_psq [blockIdx.x * HIDF + col] = s2;
}

__global__ void k_bnfin(const float* g, const float* be, int n, int nsb) {
    int c = threadIdx.x;                // 128
    float s = 0.0f, s2 = 0.0f;
    for (int b = 0; b < nsb; b++) {
        s  += g_psum[b * HIDF + c];
        s2 += g_psq [b * HIDF + c];
    }
    float inv_n = 1.0f / (float)n;
    float mean = s * inv_n;
    float var = s2 * inv_n - mean * mean;
    float sc = g[c] * rsqrtf(var + EPSF);
    g_bn[c] = sc;
    g_bn[HIDF + c] = be[c] - mean * sc;
}

__global__ void k_bnapply(int n) {
    int i = blockIdx.x * blockDim.x + threadIdx.x;   // float4 index, n*32
    if (i < n * 32) {
        int c4 = i & 31;
        float4 v  = ((float4*)g_bufA)[i];
        float4 sc = ((const float4*)g_bn)[c4];
        float4 sh = ((const float4*)g_bn)[32 + c4];
        v.x = fmaxf(v.x * sc.x + sh.x, 0.0f);
        v.y = fmaxf(v.y * sc.y + sh.y, 0.0f);
        v.z = fmaxf(v.z * sc.z + sh.z, 0.0f);
        v.w = fmaxf(v.w * sc.w + sh.w, 0.0f);
        ((float4*)g_bufA)[i] = v;
    }
}

// ---------------- layer1 aggregation (128 feats): bufA -> bufB, warp/node ----------------
__global__ void k_agg128(int n) {
    int t = blockIdx.x * blockDim.x + threadIdx.x;
    int node = t >> 5, lane = t & 31;
    if (node < n) {
        float di = g_dinv[node];
        float sc = di * di;
        float4 a = ((const float4*)g_bufA)[node * 32 + lane];
        a.x *= sc; a.y *= sc; a.z *= sc; a.w *= sc;
        int s0 = g_rowptr[node], s1 = g_rowptr[node + 1];
        for (int s = s0; s < s1; s++) {
            int src = g_src[s];               // broadcast within warp
            float nv = g_nrm[s];
            float4 v = ((const float4*)g_bufA)[src * 32 + lane];
            a.x += v.x * nv; a.y += v.y * nv; a.z += v.z * nv; a.w += v.w * nv;
        }
        ((float4*)g_bufB)[node * 32 + lane] = a;
    }
}

// ---------------- GEMM1: (N x 128) @ (128 x 128) + b -> bufA ----------------
__global__ void k_gemm1(const float* W, const float* bias, int n) {
    __shared__ float As[16][64];
    __shared__ float Bs[16][128];
    int tid = threadIdx.x;              // 256
    int trow = tid >> 5;
    int tcol = tid & 31;
    int r0 = trow * 8, c0 = tcol * 4;
    int rowBase = blockIdx.x * 64;
    float acc[8][4];
#pragma unroll
    for (int i = 0; i < 8; i++)
#pragma unroll
        for (int j = 0; j < 4; j++) acc[i][j] = 0.0f;

    for (int kk = 0; kk < HIDF; kk += 16) {
        {   // A tile: 64 rows x 16 k (transposed into As[k][r])
            int r = tid >> 2;
            int kq = (tid & 3) * 4;
            int row = rowBase + r;
            float4 a = make_float4(0.f, 0.f, 0.f, 0.f);
            if (row < n) a = *(const float4*)&g_bufB[row * HIDF + kk + kq];
            As[kq + 0][r] = a.x; As[kq + 1][r] = a.y;
            As[kq + 2][r] = a.z; As[kq + 3][r] = a.w;
        }
        {   // B tile: 16 x 128
            int k = tid >> 4;
            int cq = (tid & 15) * 8;
            const float* wp = &W[(kk + k) * HIDF + cq];
            *(float4*)&Bs[k][cq]     = *(const float4*)wp;
            *(float4*)&Bs[k][cq + 4] = *(const float4*)(wp + 4);
        }
        __syncthreads();
#pragma unroll
        for (int k = 0; k < 16; k++) {
            float4 b = *(const float4*)&Bs[k][c0];
            float4 a0 = *(const float4*)&As[k][r0];
            float4 a1 = *(const float4*)&As[k][r0 + 4];
            float ar[8] = {a0.x, a0.y, a0.z, a0.w, a1.x, a1.y, a1.z, a1.w};
#pragma unroll
            for (int i = 0; i < 8; i++) {
                acc[i][0] += ar[i] * b.x;
                acc[i][1] += ar[i] * b.y;
                acc[i][2] += ar[i] * b.z;
                acc[i][3] += ar[i] * b.w;
            }
        }
        __syncthreads();
    }
#pragma unroll
    for (int i = 0; i < 8; i++) {
        int row = rowBase + r0 + i;
        if (row < n) {
            for (int j = 0; j < 4; j++)
                g_bufA[row * HIDF + c0 + j] = acc[i][j] + bias[c0 + j];
        }
    }
}

// ---------------- GEMM2: (N x 128) @ (128 x 12) -> bufB (first N*12) ----------------
__global__ void k_gemm2(const float* W, int n) {
    __shared__ float sW[HIDF * OUTF];
    __shared__ float sin[16 * HIDF];
    int tid = threadIdx.x;              // 192
    for (int idx = tid; idx < HIDF * OUTF; idx += 192) sW[idx] = W[idx];
    int base = blockIdx.x * 16;
    for (int idx = tid; idx < 16 * HIDF; idx += 192) {
        int r = idx >> 7, k = idx & 127;
        sin[idx] = (base + r < n) ? g_bufA[(base + r) * HIDF + k] : 0.0f;
    }
    __syncthreads();
    int c = tid % 12, r = tid / 12;
    if (r < 16 && base + r < n) {
        float acc = 0.0f;
#pragma unroll 8
        for (int k = 0; k < HIDF; k++) acc += sin[r * HIDF + k] * sW[k * OUTF + c];
        g_bufB[(base + r) * OUTF + c] = acc;
    }
}

// ---------------- final aggregation (12 feats): bufB -> out, fused bias ----------------
__global__ void k_agg12(float* out, const float* b2, int n) {
    int t = blockIdx.x * blockDim.x + threadIdx.x;
    int node = t >> 4, f = t & 15;
    if (node < n && f < OUTF) {
        float di = g_dinv[node];
        float a = g_bufB[node * OUTF + f] * di * di + b2[f];
        int s0 = g_rowptr[node], s1 = g_rowptr[node + 1];
        for (int s = s0; s < s1; s++)
            a += g_bufB[g_src[s] * OUTF + f] * g_nrm[s];
        out[node * OUTF + f] = a;
    }
}

// ---------------- launch ----------------
extern "C" void kernel_launch(void* const* d_in, const int* in_sizes, int n_in,
                              void* d_out, int out_size) {
    const float* x   = (const float*)d_in[0];
    const void*  ei  = d_in[1];
    const float* w   = (const float*)d_in[2];
    const float* W0  = (const float*)d_in[3];
    const float* b0  = (const float*)d_in[4];
    const float* W1  = (const float*)d_in[5];
    const float* b1  = (const float*)d_in[6];
    const float* W2  = (const float*)d_in[7];
    const float* b2  = (const float*)d_in[8];
    const float* g0  = (const float*)d_in[9];
    const float* be0 = (const float*)d_in[10];
    const float* g1  = (const float*)d_in[11];
    const float* be1 = (const float*)d_in[12];
    float* out = (float*)d_out;

    int n = in_sizes[0] / INF;
    int E = in_sizes[2];
    const int B = 256;
    int nscan = cdiv(n, 1024);
    int nsb = cdiv(n, 256);

    // dtype detect + repack edge_index into int arrays
    k_det_init<<<1, 1>>>();
    k_detect<<<cdiv(E, B), B>>>(ei, E, n);
    k_repack<<<cdiv(E, B), B>>>(ei, E);

    // CSR build
    k_zero<<<cdiv(n, B), B>>>(n);
    k_count<<<cdiv(E, B), B>>>(E);
    k_scan_block<<<nscan, 256>>>(n);
    k_scan_bsum<<<1, 128>>>(nscan);
    k_addoff<<<cdiv(n, B), B>>>(n);
    k_fillcsr<<<cdiv(E, B), B>>>(w, E);

    // normalization
    k_deg<<<cdiv(n, B), B>>>(n);
    k_normfix<<<cdiv(n, B), B>>>(n);

    // layer 0
    k_agg16<<<cdiv(n * 16, B), B>>>(x, n);
    k_gemm0<<<cdiv(n, 32), 128>>>(W0, b0, n);
    k_stats<<<nsb, 128>>>(n);
    k_bnfin<<<1, 128>>>(g0, be0, n, nsb);
    k_bnapply<<<cdiv(n * 32, B), B>>>(n);

    // layer 1
    k_agg128<<<cdiv(n * 32, B), B>>>(n);
    k_gemm1<<<cdiv(n, 64), 256>>>(W1, b1, n);
    k_stats<<<nsb, 128>>>(n);
    k_bnfin<<<1, 128>>>(g1, be1, n, nsb);
    k_bnapply<<<cdiv(n * 32, B), B>>>(n);

    // layer 2 (transform first, then aggregate narrow)
    k_gemm2<<<cdiv(n, 16), 192>>>(W2, n);
    k_agg12<<<cdiv(n * 16, B), B>>>(out, b2, n);
}